// round 11
// baseline (speedup 1.0000x reference)
#include <cuda_runtime.h>
#include <cuda_bf16.h>
#include <cstdint>

#define NN 50000
#define EE 800000

// ---------------- scratch (static device globals; no allocation) ----------------
__device__ int      g_cnt   [NN];          // zero-initialized at load; re-zeroed by scan
__device__ int      g_rowptr[NN + 1];
__device__ int      g_cursor[NN];
__device__ int      g_adj   [EE];
__device__ uint32_t g_xhi   [NN * 64];     // features as packed bf16x2 hi
__device__ uint32_t g_xlo   [NN * 64];     // features as packed bf16x2 lo
__device__ uint32_t g_whi   [640 * 64];    // all layer weights split (rows: L0 256, L1 256, L2 128)
__device__ uint32_t g_wlo   [640 * 64];
__device__ float    g_yl    [NN * 128];    // neighbor-linear pre-aggregation (f32)
__device__ float    g_yr    [NN * 128];    // root-linear (f32)

// ---------------- bf16 double-split helpers ----------------
__device__ __forceinline__ void split_bf16x2(float v0, float v1,
                                             uint32_t& hi, uint32_t& lo) {
    __nv_bfloat162 h = __floats2bfloat162_rn(v0, v1);
    float2 hf = __bfloat1622float2(h);
    __nv_bfloat162 l = __floats2bfloat162_rn(v0 - hf.x, v1 - hf.y);
    hi = *reinterpret_cast<uint32_t*>(&h);
    lo = *reinterpret_cast<uint32_t*>(&l);
}

__device__ __forceinline__ void mma_bf16(float* d, const uint32_t* a, const uint32_t* b) {
    asm volatile(
        "mma.sync.aligned.m16n8k16.row.col.f32.bf16.bf16.f32 "
        "{%0,%1,%2,%3}, {%4,%5,%6,%7}, {%8,%9}, {%0,%1,%2,%3};"
        : "+f"(d[0]), "+f"(d[1]), "+f"(d[2]), "+f"(d[3])
        : "r"(a[0]), "r"(a[1]), "r"(a[2]), "r"(a[3]), "r"(b[0]), "r"(b[1]));
}

__device__ __forceinline__ void ldsm_x4(uint32_t& d0, uint32_t& d1, uint32_t& d2, uint32_t& d3,
                                        uint32_t saddr) {
    asm volatile("ldmatrix.sync.aligned.m8n8.x4.shared.b16 {%0,%1,%2,%3}, [%4];"
                 : "=r"(d0), "=r"(d1), "=r"(d2), "=r"(d3) : "r"(saddr));
}

// ---------------- combined: split x+weights into bf16 hi/lo AND degree histogram ----------------
__global__ void split_hist_kernel(const float* __restrict__ x,
                                  const float* __restrict__ Wl0, const float* __restrict__ Wr0,
                                  const float* __restrict__ Wl1, const float* __restrict__ Wr1,
                                  const float* __restrict__ Wl2, const float* __restrict__ Wr2,
                                  const int* __restrict__ ei)
{
    const int i  = blockIdx.x * blockDim.x + threadIdx.x;
    const int XW = NN * 32;                    // float4 count for x
    const int WW = 640 * 32;                   // float4 count for all weights
    if (i < XW + WW) {
        float4 v;
        uint32_t* hi_dst;
        uint32_t* lo_dst;
        if (i < XW) {
            int r = i >> 5, q = i & 31;
            v = *(const float4*)(x + r * 128 + q * 4);
            hi_dst = g_xhi + r * 64 + q * 2;
            lo_dst = g_xlo + r * 64 + q * 2;
        } else {
            int j = i - XW;
            int wrow = j >> 5, q = j & 31;
            const float* src;
            if (wrow < 256)      src = (wrow < 128) ? (Wl0 + wrow * 128)         : (Wr0 + (wrow - 128) * 128);
            else if (wrow < 512) { int r = wrow - 256; src = (r < 128) ? (Wl1 + r * 128) : (Wr1 + (r - 128) * 128); }
            else                 { int r = wrow - 512; src = (r < 64)  ? (Wl2 + r * 128) : (Wr2 + (r - 64)  * 128); }
            v = *(const float4*)(src + q * 4);
            hi_dst = g_whi + wrow * 64 + q * 2;
            lo_dst = g_wlo + wrow * 64 + q * 2;
        }
        uint32_t h0, l0, h1, l1;
        split_bf16x2(v.x, v.y, h0, l0);
        split_bf16x2(v.z, v.w, h1, l1);
        hi_dst[0] = h0; hi_dst[1] = h1;
        lo_dst[0] = l0; lo_dst[1] = l1;
    } else {
        int e = i - (XW + WW);
        if (e < EE) atomicAdd(&g_cnt[ei[EE + e]], 1);
    }
}

// ---------------- CSR build ----------------
// scan + re-zero cnt (so hist finds zeros on the next call)
__global__ void __launch_bounds__(1024, 1) scan_kernel() {
    __shared__ int sums[1024];
    const int t  = threadIdx.x;
    const int CH = (NN + 1023) / 1024;   // 49
    const int base = t * CH;
    int s = 0;
    for (int i = 0; i < CH; i++) {
        int idx = base + i;
        if (idx < NN) s += g_cnt[idx];
    }
    sums[t] = s;
    __syncthreads();
    for (int off = 1; off < 1024; off <<= 1) {
        int v = (t >= off) ? sums[t - off] : 0;
        __syncthreads();
        sums[t] += v;
        __syncthreads();
    }
    int run = (t == 0) ? 0 : sums[t - 1];
    for (int i = 0; i < CH; i++) {
        int idx = base + i;
        if (idx < NN) {
            int c = g_cnt[idx];
            g_rowptr[idx] = run;
            g_cursor[idx] = run;
            run += c;
            g_cnt[idx] = 0;
        }
    }
    if (t == 1023) g_rowptr[NN] = run;
}

__global__ void fill_kernel(const int* __restrict__ ei) {
    int i = blockIdx.x * blockDim.x + threadIdx.x;
    if (i < EE) {
        int s = ei[i];
        int d = ei[EE + i];
        int p = atomicAdd(&g_cursor[d], 1);
        g_adj[p] = s;
    }
}

// ---------------- bf16 split mma.sync dual GEMM: [yl|yr] = X @ [Wl|Wr]^T ----------------
// Block tile: BM=128 rows x 64 cols, 104KB SMEM -> 2 CTAs/SM (16 warps).
// 8 warps: 4 (M) x 2 (N), each warp 32x32 via m16n8k16.
// Fragment loads via ldmatrix.x4 (8 per k-step instead of 32 scalar LDS).
// acc += AhiBhi + AloBhi + AhiBlo  (drops lo*lo ~ 2^-18).
template <int DOUT>
__global__ void __launch_bounds__(256, 2)
tc_gemm_kernel(int wrow0)
{
    constexpr int PP  = 68;                 // pitch in u32 (bf16 pairs)
    constexpr int XHI = 0;
    constexpr int XLO = 128 * PP;           // 8704
    constexpr int WHI = 2 * 128 * PP;       // 17408
    constexpr int WLO = 2 * 128 * PP + 64 * PP;   // 21760
    // total u32 = 26112 -> 104448 bytes

    extern __shared__ uint32_t sm[];

    const int tid   = threadIdx.x;
    const int lane  = tid & 31;
    const int wid   = tid >> 5;
    const int mwarp = wid & 3;              // 0..3
    const int nwarp = wid >> 2;             // 0..1
    const int row0  = blockIdx.x * 128;
    const int col0  = blockIdx.y * 64;      // within [0, 2*DOUT)

    // ---- stage X tile (128 rows x 16 uint4 per buffer) ----
    for (int idx = tid; idx < 128 * 16; idx += 256) {
        int r = idx >> 4, q4 = idx & 15;
        int grow = row0 + r;
        uint4 h = make_uint4(0u, 0u, 0u, 0u), l = make_uint4(0u, 0u, 0u, 0u);
        if (grow < NN) {
            h = *(const uint4*)(g_xhi + grow * 64 + q4 * 4);
            l = *(const uint4*)(g_xlo + grow * 64 + q4 * 4);
        }
        *(uint4*)&sm[XHI + r * PP + q4 * 4] = h;
        *(uint4*)&sm[XLO + r * PP + q4 * 4] = l;
    }
    // ---- stage W tile (64 rows x 16 uint4 per buffer) ----
    for (int idx = tid; idx < 64 * 16; idx += 256) {
        int r = idx >> 4, q4 = idx & 15;
        int wrow = wrow0 + col0 + r;
        *(uint4*)&sm[WHI + r * PP + q4 * 4] = *(const uint4*)(g_whi + wrow * 64 + q4 * 4);
        *(uint4*)&sm[WLO + r * PP + q4 * 4] = *(const uint4*)(g_wlo + wrow * 64 + q4 * 4);
    }
    __syncthreads();

    const uint32_t sbase = (uint32_t)__cvta_generic_to_shared(sm);

    // ldmatrix lane-address precompute (byte addresses into shared space)
    // A (per mt): matrices [rows0-7,k0-7][rows8-15,k0-7][rows0-7,k8-15][rows8-15,k8-15]
    //   row = rb + (lane&15), koff_u32 = (lane>>4)*4
    const int a_row_off = (lane & 15);
    const int a_koff    = (lane >> 4) << 2;
    uint32_t a_hi_addr[2], a_lo_addr[2];
#pragma unroll
    for (int mt = 0; mt < 2; mt++) {
        int rb = mwarp * 32 + mt * 16;
        uint32_t off = (uint32_t)((rb + a_row_off) * PP + a_koff);
        a_hi_addr[mt] = sbase + (XHI + off) * 4u;
        a_lo_addr[mt] = sbase + (XLO + off) * 4u;
    }
    // B (per nt-pair): d0,d1 = b0,b1 of nt; d2,d3 = b0,b1 of nt+1
    //   n-row = nb + (lane>>4)*8 + (lane&7), koff_u32 = (lane&8) ? 4 : 0
    const int b_row_off = ((lane >> 4) << 3) + (lane & 7);
    const int b_koff    = (lane & 8) ? 4 : 0;
    uint32_t b_hi_addr[2], b_lo_addr[2];
#pragma unroll
    for (int np = 0; np < 2; np++) {
        int nb = nwarp * 32 + np * 16;
        uint32_t off = (uint32_t)((nb + b_row_off) * PP + b_koff);
        b_hi_addr[np] = sbase + (WHI + off) * 4u;
        b_lo_addr[np] = sbase + (WLO + off) * 4u;
    }

    const int r8 = lane >> 2;    // 0..7
    const int c4 = lane & 3;     // 0..3

    float acc[2][4][4];
#pragma unroll
    for (int mt = 0; mt < 2; mt++)
#pragma unroll
        for (int nt = 0; nt < 4; nt++)
#pragma unroll
            for (int j = 0; j < 4; j++) acc[mt][nt][j] = 0.f;

#pragma unroll
    for (int kt = 0; kt < 8; kt++) {
        const uint32_t kb = (uint32_t)kt * 32u;   // 8 u32 per k-tile = 32 bytes
        uint32_t ahi[2][4], alo[2][4];
#pragma unroll
        for (int mt = 0; mt < 2; mt++) {
            ldsm_x4(ahi[mt][0], ahi[mt][1], ahi[mt][2], ahi[mt][3], a_hi_addr[mt] + kb);
            ldsm_x4(alo[mt][0], alo[mt][1], alo[mt][2], alo[mt][3], a_lo_addr[mt] + kb);
        }
        uint32_t bhi[4][2], blo[4][2];
#pragma unroll
        for (int np = 0; np < 2; np++) {
            ldsm_x4(bhi[np*2][0], bhi[np*2][1], bhi[np*2+1][0], bhi[np*2+1][1], b_hi_addr[np] + kb);
            ldsm_x4(blo[np*2][0], blo[np*2][1], blo[np*2+1][0], blo[np*2+1][1], b_lo_addr[np] + kb);
        }
#pragma unroll
        for (int mt = 0; mt < 2; mt++)
#pragma unroll
            for (int nt = 0; nt < 4; nt++) {
                mma_bf16(acc[mt][nt], ahi[mt], bhi[nt]);
                mma_bf16(acc[mt][nt], alo[mt], bhi[nt]);
                mma_bf16(acc[mt][nt], ahi[mt], blo[nt]);
            }
    }

    // ---- epilogue: scatter accumulators to g_yl / g_yr ----
#pragma unroll
    for (int mt = 0; mt < 2; mt++) {
        int rowg0 = row0 + mwarp * 32 + mt * 16 + r8;
#pragma unroll
        for (int nt = 0; nt < 4; nt++) {
            int colq = col0 + nwarp * 32 + nt * 8 + 2 * c4;   // within D2
            float* dstbase;
            int col;
            if (colq < DOUT) { dstbase = g_yl; col = colq; }
            else             { dstbase = g_yr; col = colq - DOUT; }
            if (rowg0 < NN)
                *(float2*)(dstbase + rowg0 * DOUT + col)
                    = make_float2(acc[mt][nt][0], acc[mt][nt][1]);
            if (rowg0 + 8 < NN)
                *(float2*)(dstbase + (rowg0 + 8) * DOUT + col)
                    = make_float2(acc[mt][nt][2], acc[mt][nt][3]);
        }
    }
}

// ---------------- fused CSR gather + mean + bias + root + BN + ReLU -> split h ----------------
__global__ void gather_fin128_kernel(const float* __restrict__ bl,
                                     const float* __restrict__ g,
                                     const float* __restrict__ b,
                                     const float* __restrict__ rm,
                                     const float* __restrict__ rv)
{
    int w    = (blockIdx.x * blockDim.x + threadIdx.x) >> 5;
    int lane = threadIdx.x & 31;
    if (w >= NN) return;

    int beg = g_rowptr[w];
    int end = g_rowptr[w + 1];

    const float4* yl4 = (const float4*)g_yl;
    float4 acc = make_float4(0.f, 0.f, 0.f, 0.f);

    for (int base = beg; base < end; base += 32) {
        int n  = min(32, end - base);
        int id = (base + lane < end) ? g_adj[base + lane] : 0;
#pragma unroll 8
        for (int j = 0; j < n; j++) {
            int s = __shfl_sync(0xffffffffu, id, j);
            float4 v = yl4[s * 32 + lane];
            acc.x += v.x; acc.y += v.y; acc.z += v.z; acc.w += v.w;
        }
    }

    float inv = (end > beg) ? 1.0f / (float)(end - beg) : 1.0f;

    float4 BL = ((const float4*)bl)[lane];
    float4 G  = ((const float4*)g )[lane];
    float4 B  = ((const float4*)b )[lane];
    float4 RM = ((const float4*)rm)[lane];
    float4 RV = ((const float4*)rv)[lane];
    float4 y  = ((const float4*)g_yr)[w * 32 + lane];

    float sx = G.x * rsqrtf(RV.x + 1e-5f);
    float sy = G.y * rsqrtf(RV.y + 1e-5f);
    float sz = G.z * rsqrtf(RV.z + 1e-5f);
    float sw = G.w * rsqrtf(RV.w + 1e-5f);

    float ox = fmaxf((acc.x * inv + BL.x + y.x - RM.x) * sx + B.x, 0.f);
    float oy = fmaxf((acc.y * inv + BL.y + y.y - RM.y) * sy + B.y, 0.f);
    float oz = fmaxf((acc.z * inv + BL.z + y.z - RM.z) * sz + B.z, 0.f);
    float ow = fmaxf((acc.w * inv + BL.w + y.w - RM.w) * sw + B.w, 0.f);

    // write next-layer features pre-split (hi/lo bf16x2)
    uint32_t h0, l0, h1, l1;
    split_bf16x2(ox, oy, h0, l0);
    split_bf16x2(oz, ow, h1, l1);
    g_xhi[w * 64 + 2 * lane]     = h0;
    g_xhi[w * 64 + 2 * lane + 1] = h1;
    g_xlo[w * 64 + 2 * lane]     = l0;
    g_xlo[w * 64 + 2 * lane + 1] = l1;
}

// ---------------- layer 2: fused gather + finalize + row L2 normalize -> out ----------------
__global__ void gather_fin64_norm_kernel(const float* __restrict__ bl,
                                         const float* __restrict__ g,
                                         const float* __restrict__ b,
                                         const float* __restrict__ rm,
                                         const float* __restrict__ rv,
                                         float* __restrict__ out)
{
    int w    = (blockIdx.x * blockDim.x + threadIdx.x) >> 5;
    int lane = threadIdx.x & 31;
    if (w >= NN) return;

    int beg = g_rowptr[w];
    int end = g_rowptr[w + 1];

    const float2* yl2 = (const float2*)g_yl;
    float2 acc = make_float2(0.f, 0.f);

    for (int base = beg; base < end; base += 32) {
        int n  = min(32, end - base);
        int id = (base + lane < end) ? g_adj[base + lane] : 0;
#pragma unroll 8
        for (int j = 0; j < n; j++) {
            int s = __shfl_sync(0xffffffffu, id, j);
            float2 v = yl2[s * 32 + lane];
            acc.x += v.x; acc.y += v.y;
        }
    }

    float inv = (end > beg) ? 1.0f / (float)(end - beg) : 1.0f;

    float2 BL = ((const float2*)bl)[lane];
    float2 G  = ((const float2*)g )[lane];
    float2 B  = ((const float2*)b )[lane];
    float2 RM = ((const float2*)rm)[lane];
    float2 RV = ((const float2*)rv)[lane];
    float2 y  = ((const float2*)g_yr)[w * 32 + lane];

    float v0 = (acc.x * inv + BL.x + y.x - RM.x) * (G.x * rsqrtf(RV.x + 1e-5f)) + B.x;
    float v1 = (acc.y * inv + BL.y + y.y - RM.y) * (G.y * rsqrtf(RV.y + 1e-5f)) + B.y;

    float s = v0 * v0 + v1 * v1;
#pragma unroll
    for (int off = 16; off > 0; off >>= 1)
        s += __shfl_xor_sync(0xffffffffu, s, off);

    float scale = 1.0f / fmaxf(sqrtf(s), 1e-12f);
    ((float2*)out)[w * 32 + lane] = make_float2(v0 * scale, v1 * scale);
}

// ---------------- launch ----------------
extern "C" void kernel_launch(void* const* d_in, const int* in_sizes, int n_in,
                              void* d_out, int out_size)
{
    const float* x  = (const float*)d_in[0];
    const int*   ei = (const int*)d_in[1];
    auto P = [&](int layer, int j) { return (const float*)d_in[2 + layer * 7 + j]; };
    // j: 0=Wl, 1=bl, 2=Wr, 3=g, 4=b, 5=rm, 6=rv

    // one-time stream/event setup (created before graph capture on first call;
    // identical launch DAG every call)
    static cudaStream_t s2 = [] {
        cudaStream_t s; cudaStreamCreateWithFlags(&s, cudaStreamNonBlocking); return s;
    }();
    static cudaEvent_t e1 = [] {
        cudaEvent_t e; cudaEventCreateWithFlags(&e, cudaEventDisableTiming); return e;
    }();
    static cudaEvent_t e2 = [] {
        cudaEvent_t e; cudaEventCreateWithFlags(&e, cudaEventDisableTiming); return e;
    }();

    const int SMEM = (2 * 128 * 68 + 2 * 64 * 68) * 4;  // 104448 bytes -> 2 CTAs/SM
    cudaFuncSetAttribute(tc_gemm_kernel<128>, cudaFuncAttributeMaxDynamicSharedMemorySize, SMEM);
    cudaFuncSetAttribute(tc_gemm_kernel<64>,  cudaFuncAttributeMaxDynamicSharedMemorySize, SMEM);

    const int NT = (NN + 127) / 128;   // 391 M-tiles
    const int COMBO_N = NN * 32 + 640 * 32 + EE;

    // (1) split x+weights AND degree histogram (fused) — main stream
    split_hist_kernel<<<(COMBO_N + 255) / 256, 256>>>(x, P(0,0), P(0,2), P(1,0), P(1,2),
                                                      P(2,0), P(2,2), ei);
    cudaEventRecord(e1, 0);

    // (2-3) CSR: scan + fill — main stream
    scan_kernel<<<1, 1024>>>();
    fill_kernel<<<(EE + 255) / 256, 256>>>(ei);

    // (4) layer-0 GEMM on side stream, concurrent with scan+fill
    cudaStreamWaitEvent(s2, e1, 0);
    tc_gemm_kernel<128><<<dim3(NT, 4), 256, SMEM, s2>>>(0);
    cudaEventRecord(e2, s2);

    // join: gather0 needs fill (main) + gemm0 (s2)
    cudaStreamWaitEvent(0, e2, 0);
    gather_fin128_kernel<<<(NN + 7) / 8, 256>>>(P(0,1), P(0,3), P(0,4), P(0,5), P(0,6));

    // layer 1 (serial)
    tc_gemm_kernel<128><<<dim3(NT, 4), 256, SMEM>>>(256);
    gather_fin128_kernel<<<(NN + 7) / 8, 256>>>(P(1,1), P(1,3), P(1,4), P(1,5), P(1,6));

    // layer 2 (serial)
    tc_gemm_kernel<64><<<dim3(NT, 2), 256, SMEM>>>(512);
    gather_fin64_norm_kernel<<<(NN + 7) / 8, 256>>>(P(2,1), P(2,3), P(2,4), P(2,5), P(2,6),
                                                    (float*)d_out);
}

// round 12
// speedup vs baseline: 1.0429x; 1.0429x over previous
#include <cuda_runtime.h>
#include <cuda_bf16.h>
#include <cstdint>

#define NN 50000
#define EE 800000

// ---------------- scratch (static device globals; no allocation) ----------------
__device__ int      g_cnt   [NN];          // zero-initialized at load; re-zeroed by scan
__device__ int      g_rowptr[NN + 1];
__device__ int      g_cursor[NN];
__device__ int      g_adj   [EE];
__device__ uint32_t g_xhi   [NN * 64];     // features as packed bf16x2 hi
__device__ uint32_t g_xlo   [NN * 64];     // features as packed bf16x2 lo
__device__ uint32_t g_whi   [640 * 64];    // all layer weights split (rows: L0 256, L1 256, L2 128)
__device__ uint32_t g_wlo   [640 * 64];
__device__ float    g_yl    [NN * 128];    // neighbor-linear pre-aggregation (f32)
__device__ float    g_yr    [NN * 128];    // root-linear (f32)

// ---------------- bf16 double-split helpers ----------------
__device__ __forceinline__ void split_bf16x2(float v0, float v1,
                                             uint32_t& hi, uint32_t& lo) {
    __nv_bfloat162 h = __floats2bfloat162_rn(v0, v1);
    float2 hf = __bfloat1622float2(h);
    __nv_bfloat162 l = __floats2bfloat162_rn(v0 - hf.x, v1 - hf.y);
    hi = *reinterpret_cast<uint32_t*>(&h);
    lo = *reinterpret_cast<uint32_t*>(&l);
}

__device__ __forceinline__ void mma_bf16(float* d, const uint32_t* a, const uint32_t* b) {
    asm volatile(
        "mma.sync.aligned.m16n8k16.row.col.f32.bf16.bf16.f32 "
        "{%0,%1,%2,%3}, {%4,%5,%6,%7}, {%8,%9}, {%0,%1,%2,%3};"
        : "+f"(d[0]), "+f"(d[1]), "+f"(d[2]), "+f"(d[3])
        : "r"(a[0]), "r"(a[1]), "r"(a[2]), "r"(a[3]), "r"(b[0]), "r"(b[1]));
}

__device__ __forceinline__ void ldsm_x4(uint32_t& d0, uint32_t& d1, uint32_t& d2, uint32_t& d3,
                                        uint32_t saddr) {
    asm volatile("ldmatrix.sync.aligned.m8n8.x4.shared.b16 {%0,%1,%2,%3}, [%4];"
                 : "=r"(d0), "=r"(d1), "=r"(d2), "=r"(d3) : "r"(saddr));
}

__device__ __forceinline__ void cp16(uint32_t dst, const void* src, bool valid) {
    int sz = valid ? 16 : 0;
    asm volatile("cp.async.cg.shared.global [%0], [%1], 16, %2;"
                 :: "r"(dst), "l"(src), "r"(sz) : "memory");
}

__device__ __forceinline__ void cp_commit() {
    asm volatile("cp.async.commit_group;" ::: "memory");
}

template <int N>
__device__ __forceinline__ void cp_wait() {
    asm volatile("cp.async.wait_group %0;" :: "n"(N) : "memory");
}

// ---------------- combined: split x+weights into bf16 hi/lo AND degree histogram ----------------
__global__ void split_hist_kernel(const float* __restrict__ x,
                                  const float* __restrict__ Wl0, const float* __restrict__ Wr0,
                                  const float* __restrict__ Wl1, const float* __restrict__ Wr1,
                                  const float* __restrict__ Wl2, const float* __restrict__ Wr2,
                                  const int* __restrict__ ei)
{
    const int i  = blockIdx.x * blockDim.x + threadIdx.x;
    const int XW = NN * 32;                    // float4 count for x
    const int WW = 640 * 32;                   // float4 count for all weights
    if (i < XW + WW) {
        float4 v;
        uint32_t* hi_dst;
        uint32_t* lo_dst;
        if (i < XW) {
            int r = i >> 5, q = i & 31;
            v = *(const float4*)(x + r * 128 + q * 4);
            hi_dst = g_xhi + r * 64 + q * 2;
            lo_dst = g_xlo + r * 64 + q * 2;
        } else {
            int j = i - XW;
            int wrow = j >> 5, q = j & 31;
            const float* src;
            if (wrow < 256)      src = (wrow < 128) ? (Wl0 + wrow * 128)         : (Wr0 + (wrow - 128) * 128);
            else if (wrow < 512) { int r = wrow - 256; src = (r < 128) ? (Wl1 + r * 128) : (Wr1 + (r - 128) * 128); }
            else                 { int r = wrow - 512; src = (r < 64)  ? (Wl2 + r * 128) : (Wr2 + (r - 64)  * 128); }
            v = *(const float4*)(src + q * 4);
            hi_dst = g_whi + wrow * 64 + q * 2;
            lo_dst = g_wlo + wrow * 64 + q * 2;
        }
        uint32_t h0, l0, h1, l1;
        split_bf16x2(v.x, v.y, h0, l0);
        split_bf16x2(v.z, v.w, h1, l1);
        hi_dst[0] = h0; hi_dst[1] = h1;
        lo_dst[0] = l0; lo_dst[1] = l1;
    } else {
        int e = i - (XW + WW);
        if (e < EE) atomicAdd(&g_cnt[ei[EE + e]], 1);
    }
}

// ---------------- CSR build ----------------
// scan + re-zero cnt (so hist finds zeros on the next call)
__global__ void __launch_bounds__(1024, 1) scan_kernel() {
    __shared__ int sums[1024];
    const int t  = threadIdx.x;
    const int CH = (NN + 1023) / 1024;   // 49
    const int base = t * CH;
    int s = 0;
    for (int i = 0; i < CH; i++) {
        int idx = base + i;
        if (idx < NN) s += g_cnt[idx];
    }
    sums[t] = s;
    __syncthreads();
    for (int off = 1; off < 1024; off <<= 1) {
        int v = (t >= off) ? sums[t - off] : 0;
        __syncthreads();
        sums[t] += v;
        __syncthreads();
    }
    int run = (t == 0) ? 0 : sums[t - 1];
    for (int i = 0; i < CH; i++) {
        int idx = base + i;
        if (idx < NN) {
            int c = g_cnt[idx];
            g_rowptr[idx] = run;
            g_cursor[idx] = run;
            run += c;
            g_cnt[idx] = 0;
        }
    }
    if (t == 1023) g_rowptr[NN] = run;
}

__global__ void fill_kernel(const int* __restrict__ ei) {
    int i = blockIdx.x * blockDim.x + threadIdx.x;
    if (i < EE) {
        int s = ei[i];
        int d = ei[EE + i];
        int p = atomicAdd(&g_cursor[d], 1);
        g_adj[p] = s;
    }
}

// ---------------- bf16 split mma.sync dual GEMM: [yl|yr] = X @ [Wl|Wr]^T ----------------
// Block tile: BM=128 rows x 64 cols. 2-stage cp.async k-pipeline (K halves of 64).
// SMEM 110.6KB -> 2 CTAs/SM. 8 warps: 4(M) x 2(N), warp tile 32x32 via m16n8k16.
// acc += AhiBhi + AloBhi + AhiBlo  (drops lo*lo ~ 2^-18).
template <int DOUT>
__global__ void __launch_bounds__(256, 2)
tc_gemm_kernel(int wrow0)
{
    constexpr int PP   = 36;                    // per-stage pitch in u32 (32 data + 4 pad)
    constexpr int XHSZ = 128 * PP;              // 4608
    constexpr int WHSZ = 64 * PP;               // 2304
    constexpr int SSZ  = 2 * XHSZ + 2 * WHSZ;   // 13824 u32 per stage
    // layout per stage: [XHI | XLO | WHI | WLO]; total 27648 u32 = 110592 B

    extern __shared__ uint32_t sm[];

    const int tid   = threadIdx.x;
    const int lane  = tid & 31;
    const int wid   = tid >> 5;
    const int mwarp = wid & 3;              // 0..3
    const int nwarp = wid >> 2;             // 0..1
    const int row0  = blockIdx.x * 128;
    const int col0  = blockIdx.y * 64;      // within [0, 2*DOUT)
    const uint32_t sbase = (uint32_t)__cvta_generic_to_shared(sm);

    // ---- issue both k-half stages via cp.async ----
#pragma unroll
    for (int kk = 0; kk < 2; kk++) {
        const uint32_t st = (uint32_t)kk * SSZ;
        // X: 128 rows x 8 uint4 per component
        for (int idx = tid; idx < 128 * 8; idx += 256) {
            int r = idx >> 3, q = idx & 7;
            int grow = row0 + r;
            bool v = (grow < NN);
            const uint32_t* shi = g_xhi + grow * 64 + kk * 32 + q * 4;
            const uint32_t* slo = g_xlo + grow * 64 + kk * 32 + q * 4;
            cp16(sbase + (st + r * PP + q * 4) * 4u, shi, v);
            cp16(sbase + (st + XHSZ + r * PP + q * 4) * 4u, slo, v);
        }
        // W: 64 rows x 8 uint4 per component
        for (int idx = tid; idx < 64 * 8; idx += 256) {
            int r = idx >> 3, q = idx & 7;
            int wrow = wrow0 + col0 + r;
            cp16(sbase + (st + 2 * XHSZ + r * PP + q * 4) * 4u,
                 g_whi + wrow * 64 + kk * 32 + q * 4, true);
            cp16(sbase + (st + 2 * XHSZ + WHSZ + r * PP + q * 4) * 4u,
                 g_wlo + wrow * 64 + kk * 32 + q * 4, true);
        }
        cp_commit();
    }

    // ldmatrix lane offsets (relative, in u32)
    const int a_off = (lane & 15) * PP + ((lane >> 4) << 2);
    const int b_off = (((lane >> 4) << 3) + (lane & 7)) * PP + ((lane & 8) ? 4 : 0);

    const int r8 = lane >> 2;    // 0..7
    const int c4 = lane & 3;     // 0..3

    float acc[2][4][4];
#pragma unroll
    for (int mt = 0; mt < 2; mt++)
#pragma unroll
        for (int nt = 0; nt < 4; nt++)
#pragma unroll
            for (int j = 0; j < 4; j++) acc[mt][nt][j] = 0.f;

    cp_wait<1>();
    __syncthreads();

#pragma unroll
    for (int kk = 0; kk < 2; kk++) {
        const uint32_t st = (uint32_t)kk * SSZ;
        const uint32_t xhi_b = sbase + (st) * 4u;
        const uint32_t xlo_b = sbase + (st + XHSZ) * 4u;
        const uint32_t whi_b = sbase + (st + 2 * XHSZ) * 4u;
        const uint32_t wlo_b = sbase + (st + 2 * XHSZ + WHSZ) * 4u;

#pragma unroll
        for (int kt = 0; kt < 4; kt++) {
            const uint32_t kb = (uint32_t)kt * 32u;   // 8 u32 = 32 bytes per k-tile
            uint32_t ahi[2][4], alo[2][4];
#pragma unroll
            for (int mt = 0; mt < 2; mt++) {
                uint32_t ao = (uint32_t)((mwarp * 32 + mt * 16) * PP + a_off) * 4u + kb;
                ldsm_x4(ahi[mt][0], ahi[mt][1], ahi[mt][2], ahi[mt][3], xhi_b + ao);
                ldsm_x4(alo[mt][0], alo[mt][1], alo[mt][2], alo[mt][3], xlo_b + ao);
            }
            uint32_t bhi[4][2], blo[4][2];
#pragma unroll
            for (int np = 0; np < 2; np++) {
                uint32_t bo = (uint32_t)((nwarp * 32 + np * 16) * PP + b_off) * 4u + kb;
                ldsm_x4(bhi[np*2][0], bhi[np*2][1], bhi[np*2+1][0], bhi[np*2+1][1], whi_b + bo);
                ldsm_x4(blo[np*2][0], blo[np*2][1], blo[np*2+1][0], blo[np*2+1][1], wlo_b + bo);
            }
#pragma unroll
            for (int mt = 0; mt < 2; mt++)
#pragma unroll
                for (int nt = 0; nt < 4; nt++) {
                    mma_bf16(acc[mt][nt], ahi[mt], bhi[nt]);
                    mma_bf16(acc[mt][nt], alo[mt], bhi[nt]);
                    mma_bf16(acc[mt][nt], ahi[mt], blo[nt]);
                }
        }
        if (kk == 0) {
            cp_wait<0>();
            __syncthreads();
        }
    }

    // ---- epilogue: scatter accumulators to g_yl / g_yr ----
#pragma unroll
    for (int mt = 0; mt < 2; mt++) {
        int rowg0 = row0 + mwarp * 32 + mt * 16 + r8;
#pragma unroll
        for (int nt = 0; nt < 4; nt++) {
            int colq = col0 + nwarp * 32 + nt * 8 + 2 * c4;   // within D2
            float* dstbase;
            int col;
            if (colq < DOUT) { dstbase = g_yl; col = colq; }
            else             { dstbase = g_yr; col = colq - DOUT; }
            if (rowg0 < NN)
                *(float2*)(dstbase + rowg0 * DOUT + col)
                    = make_float2(acc[mt][nt][0], acc[mt][nt][1]);
            if (rowg0 + 8 < NN)
                *(float2*)(dstbase + (rowg0 + 8) * DOUT + col)
                    = make_float2(acc[mt][nt][2], acc[mt][nt][3]);
        }
    }
}

// ---------------- fused CSR gather + mean + bias + root + BN + ReLU -> split h ----------------
__global__ void gather_fin128_kernel(const float* __restrict__ bl,
                                     const float* __restrict__ g,
                                     const float* __restrict__ b,
                                     const float* __restrict__ rm,
                                     const float* __restrict__ rv)
{
    int w    = (blockIdx.x * blockDim.x + threadIdx.x) >> 5;
    int lane = threadIdx.x & 31;
    if (w >= NN) return;

    int beg = g_rowptr[w];
    int end = g_rowptr[w + 1];

    const float4* yl4 = (const float4*)g_yl;
    float4 acc = make_float4(0.f, 0.f, 0.f, 0.f);

    for (int base = beg; base < end; base += 32) {
        int n  = min(32, end - base);
        int id = (base + lane < end) ? g_adj[base + lane] : 0;
#pragma unroll 8
        for (int j = 0; j < n; j++) {
            int s = __shfl_sync(0xffffffffu, id, j);
            float4 v = yl4[s * 32 + lane];
            acc.x += v.x; acc.y += v.y; acc.z += v.z; acc.w += v.w;
        }
    }

    float inv = (end > beg) ? 1.0f / (float)(end - beg) : 1.0f;

    float4 BL = ((const float4*)bl)[lane];
    float4 G  = ((const float4*)g )[lane];
    float4 B  = ((const float4*)b )[lane];
    float4 RM = ((const float4*)rm)[lane];
    float4 RV = ((const float4*)rv)[lane];
    float4 y  = ((const float4*)g_yr)[w * 32 + lane];

    float sx = G.x * rsqrtf(RV.x + 1e-5f);
    float sy = G.y * rsqrtf(RV.y + 1e-5f);
    float sz = G.z * rsqrtf(RV.z + 1e-5f);
    float sw = G.w * rsqrtf(RV.w + 1e-5f);

    float ox = fmaxf((acc.x * inv + BL.x + y.x - RM.x) * sx + B.x, 0.f);
    float oy = fmaxf((acc.y * inv + BL.y + y.y - RM.y) * sy + B.y, 0.f);
    float oz = fmaxf((acc.z * inv + BL.z + y.z - RM.z) * sz + B.z, 0.f);
    float ow = fmaxf((acc.w * inv + BL.w + y.w - RM.w) * sw + B.w, 0.f);

    // write next-layer features pre-split (hi/lo bf16x2)
    uint32_t h0, l0, h1, l1;
    split_bf16x2(ox, oy, h0, l0);
    split_bf16x2(oz, ow, h1, l1);
    g_xhi[w * 64 + 2 * lane]     = h0;
    g_xhi[w * 64 + 2 * lane + 1] = h1;
    g_xlo[w * 64 + 2 * lane]     = l0;
    g_xlo[w * 64 + 2 * lane + 1] = l1;
}

// ---------------- layer 2: fused gather + finalize + row L2 normalize -> out ----------------
__global__ void gather_fin64_norm_kernel(const float* __restrict__ bl,
                                         const float* __restrict__ g,
                                         const float* __restrict__ b,
                                         const float* __restrict__ rm,
                                         const float* __restrict__ rv,
                                         float* __restrict__ out)
{
    int w    = (blockIdx.x * blockDim.x + threadIdx.x) >> 5;
    int lane = threadIdx.x & 31;
    if (w >= NN) return;

    int beg = g_rowptr[w];
    int end = g_rowptr[w + 1];

    const float2* yl2 = (const float2*)g_yl;
    float2 acc = make_float2(0.f, 0.f);

    for (int base = beg; base < end; base += 32) {
        int n  = min(32, end - base);
        int id = (base + lane < end) ? g_adj[base + lane] : 0;
#pragma unroll 8
        for (int j = 0; j < n; j++) {
            int s = __shfl_sync(0xffffffffu, id, j);
            float2 v = yl2[s * 32 + lane];
            acc.x += v.x; acc.y += v.y;
        }
    }

    float inv = (end > beg) ? 1.0f / (float)(end - beg) : 1.0f;

    float2 BL = ((const float2*)bl)[lane];
    float2 G  = ((const float2*)g )[lane];
    float2 B  = ((const float2*)b )[lane];
    float2 RM = ((const float2*)rm)[lane];
    float2 RV = ((const float2*)rv)[lane];
    float2 y  = ((const float2*)g_yr)[w * 32 + lane];

    float v0 = (acc.x * inv + BL.x + y.x - RM.x) * (G.x * rsqrtf(RV.x + 1e-5f)) + B.x;
    float v1 = (acc.y * inv + BL.y + y.y - RM.y) * (G.y * rsqrtf(RV.y + 1e-5f)) + B.y;

    float s = v0 * v0 + v1 * v1;
#pragma unroll
    for (int off = 16; off > 0; off >>= 1)
        s += __shfl_xor_sync(0xffffffffu, s, off);

    float scale = 1.0f / fmaxf(sqrtf(s), 1e-12f);
    ((float2*)out)[w * 32 + lane] = make_float2(v0 * scale, v1 * scale);
}

// ---------------- launch ----------------
extern "C" void kernel_launch(void* const* d_in, const int* in_sizes, int n_in,
                              void* d_out, int out_size)
{
    const float* x  = (const float*)d_in[0];
    const int*   ei = (const int*)d_in[1];
    auto P = [&](int layer, int j) { return (const float*)d_in[2 + layer * 7 + j]; };
    // j: 0=Wl, 1=bl, 2=Wr, 3=g, 4=b, 5=rm, 6=rv

    // one-time stream/event setup (created before graph capture on first call)
    static cudaStream_t s2 = [] {
        cudaStream_t s; cudaStreamCreateWithFlags(&s, cudaStreamNonBlocking); return s;
    }();
    static cudaEvent_t e1 = [] {
        cudaEvent_t e; cudaEventCreateWithFlags(&e, cudaEventDisableTiming); return e;
    }();
    static cudaEvent_t e2 = [] {
        cudaEvent_t e; cudaEventCreateWithFlags(&e, cudaEventDisableTiming); return e;
    }();

    const int SMEM = 2 * (2 * 128 * 36 + 2 * 64 * 36) * 4;  // 110592 bytes -> 2 CTAs/SM
    cudaFuncSetAttribute(tc_gemm_kernel<128>, cudaFuncAttributeMaxDynamicSharedMemorySize, SMEM);
    cudaFuncSetAttribute(tc_gemm_kernel<64>,  cudaFuncAttributeMaxDynamicSharedMemorySize, SMEM);

    const int NT = (NN + 127) / 128;   // 391 M-tiles
    const int COMBO_N = NN * 32 + 640 * 32 + EE;

    // (1) split x+weights AND degree histogram (fused) — main stream
    split_hist_kernel<<<(COMBO_N + 255) / 256, 256>>>(x, P(0,0), P(0,2), P(1,0), P(1,2),
                                                      P(2,0), P(2,2), ei);
    cudaEventRecord(e1, 0);

    // (2-3) CSR: scan + fill — main stream
    scan_kernel<<<1, 1024>>>();
    fill_kernel<<<(EE + 255) / 256, 256>>>(ei);

    // (4) layer-0 GEMM on side stream, concurrent with scan+fill
    cudaStreamWaitEvent(s2, e1, 0);
    tc_gemm_kernel<128><<<dim3(NT, 4), 256, SMEM, s2>>>(0);
    cudaEventRecord(e2, s2);

    // join: gather0 needs fill (main) + gemm0 (s2)
    cudaStreamWaitEvent(0, e2, 0);
    gather_fin128_kernel<<<(NN + 7) / 8, 256>>>(P(0,1), P(0,3), P(0,4), P(0,5), P(0,6));

    // layer 1 (serial)
    tc_gemm_kernel<128><<<dim3(NT, 4), 256, SMEM>>>(256);
    gather_fin128_kernel<<<(NN + 7) / 8, 256>>>(P(1,1), P(1,3), P(1,4), P(1,5), P(1,6));

    // layer 2 (serial)
    tc_gemm_kernel<64><<<dim3(NT, 2), 256, SMEM>>>(512);
    gather_fin64_norm_kernel<<<(NN + 7) / 8, 256>>>(P(2,1), P(2,3), P(2,4), P(2,5), P(2,6),
                                                    (float*)d_out);
}

// round 13
// speedup vs baseline: 1.0751x; 1.0308x over previous
#include <cuda_runtime.h>
#include <cuda_bf16.h>
#include <cstdint>

#define NN 50000
#define EE 800000

// ---------------- scratch (static device globals; no allocation) ----------------
__device__ int      g_cnt   [NN];          // zero-initialized at load; re-zeroed by scan
__device__ int      g_rowptr[NN + 1];
__device__ int      g_cursor[NN];
__device__ int      g_adj   [EE];
__device__ uint32_t g_xhi   [NN * 64];     // features as packed bf16x2 hi
__device__ uint32_t g_xlo   [NN * 64];     // features as packed bf16x2 lo
__device__ uint32_t g_whi   [640 * 64];    // all layer weights split (rows: L0 256, L1 256, L2 128)
__device__ uint32_t g_wlo   [640 * 64];
__device__ float    g_yl    [NN * 128];    // neighbor-linear pre-aggregation (f32)
__device__ float    g_yr    [NN * 128];    // root-linear (f32)

// ---------------- bf16 double-split helpers ----------------
__device__ __forceinline__ void split_bf16x2(float v0, float v1,
                                             uint32_t& hi, uint32_t& lo) {
    __nv_bfloat162 h = __floats2bfloat162_rn(v0, v1);
    float2 hf = __bfloat1622float2(h);
    __nv_bfloat162 l = __floats2bfloat162_rn(v0 - hf.x, v1 - hf.y);
    hi = *reinterpret_cast<uint32_t*>(&h);
    lo = *reinterpret_cast<uint32_t*>(&l);
}

__device__ __forceinline__ void mma_bf16(float* d, const uint32_t* a, const uint32_t* b) {
    asm volatile(
        "mma.sync.aligned.m16n8k16.row.col.f32.bf16.bf16.f32 "
        "{%0,%1,%2,%3}, {%4,%5,%6,%7}, {%8,%9}, {%0,%1,%2,%3};"
        : "+f"(d[0]), "+f"(d[1]), "+f"(d[2]), "+f"(d[3])
        : "r"(a[0]), "r"(a[1]), "r"(a[2]), "r"(a[3]), "r"(b[0]), "r"(b[1]));
}

__device__ __forceinline__ void ldsm_x4(uint32_t& d0, uint32_t& d1, uint32_t& d2, uint32_t& d3,
                                        uint32_t saddr) {
    asm volatile("ldmatrix.sync.aligned.m8n8.x4.shared.b16 {%0,%1,%2,%3}, [%4];"
                 : "=r"(d0), "=r"(d1), "=r"(d2), "=r"(d3) : "r"(saddr));
}

__device__ __forceinline__ void cp16(uint32_t dst, const void* src, bool valid) {
    int sz = valid ? 16 : 0;
    asm volatile("cp.async.cg.shared.global [%0], [%1], 16, %2;"
                 :: "r"(dst), "l"(src), "r"(sz) : "memory");
}

__device__ __forceinline__ void cp_commit() {
    asm volatile("cp.async.commit_group;" ::: "memory");
}

template <int N>
__device__ __forceinline__ void cp_wait() {
    asm volatile("cp.async.wait_group %0;" :: "n"(N) : "memory");
}

// ---------------- combined: split x+weights into bf16 hi/lo AND degree histogram ----------------
__global__ void split_hist_kernel(const float* __restrict__ x,
                                  const float* __restrict__ Wl0, const float* __restrict__ Wr0,
                                  const float* __restrict__ Wl1, const float* __restrict__ Wr1,
                                  const float* __restrict__ Wl2, const float* __restrict__ Wr2,
                                  const int* __restrict__ ei)
{
    const int i  = blockIdx.x * blockDim.x + threadIdx.x;
    const int XW = NN * 32;                    // float4 count for x
    const int WW = 640 * 32;                   // float4 count for all weights
    if (i < XW + WW) {
        float4 v;
        uint32_t* hi_dst;
        uint32_t* lo_dst;
        if (i < XW) {
            int r = i >> 5, q = i & 31;
            v = *(const float4*)(x + r * 128 + q * 4);
            hi_dst = g_xhi + r * 64 + q * 2;
            lo_dst = g_xlo + r * 64 + q * 2;
        } else {
            int j = i - XW;
            int wrow = j >> 5, q = j & 31;
            const float* src;
            if (wrow < 256)      src = (wrow < 128) ? (Wl0 + wrow * 128)         : (Wr0 + (wrow - 128) * 128);
            else if (wrow < 512) { int r = wrow - 256; src = (r < 128) ? (Wl1 + r * 128) : (Wr1 + (r - 128) * 128); }
            else                 { int r = wrow - 512; src = (r < 64)  ? (Wl2 + r * 128) : (Wr2 + (r - 64)  * 128); }
            v = *(const float4*)(src + q * 4);
            hi_dst = g_whi + wrow * 64 + q * 2;
            lo_dst = g_wlo + wrow * 64 + q * 2;
        }
        uint32_t h0, l0, h1, l1;
        split_bf16x2(v.x, v.y, h0, l0);
        split_bf16x2(v.z, v.w, h1, l1);
        hi_dst[0] = h0; hi_dst[1] = h1;
        lo_dst[0] = l0; lo_dst[1] = l1;
    } else {
        int e = i - (XW + WW);
        if (e < EE) atomicAdd(&g_cnt[ei[EE + e]], 1);
    }
}

// ---------------- CSR build ----------------
// scan + re-zero cnt (so hist finds zeros on the next call)
__global__ void __launch_bounds__(1024, 1) scan_kernel() {
    __shared__ int sums[1024];
    const int t  = threadIdx.x;
    const int CH = (NN + 1023) / 1024;   // 49
    const int base = t * CH;
    int s = 0;
    for (int i = 0; i < CH; i++) {
        int idx = base + i;
        if (idx < NN) s += g_cnt[idx];
    }
    sums[t] = s;
    __syncthreads();
    for (int off = 1; off < 1024; off <<= 1) {
        int v = (t >= off) ? sums[t - off] : 0;
        __syncthreads();
        sums[t] += v;
        __syncthreads();
    }
    int run = (t == 0) ? 0 : sums[t - 1];
    for (int i = 0; i < CH; i++) {
        int idx = base + i;
        if (idx < NN) {
            int c = g_cnt[idx];
            g_rowptr[idx] = run;
            g_cursor[idx] = run;
            run += c;
            g_cnt[idx] = 0;
        }
    }
    if (t == 1023) g_rowptr[NN] = run;
}

__global__ void fill_kernel(const int* __restrict__ ei) {
    int i = blockIdx.x * blockDim.x + threadIdx.x;
    if (i < EE) {
        int s = ei[i];
        int d = ei[EE + i];
        int p = atomicAdd(&g_cursor[d], 1);
        g_adj[p] = s;
    }
}

// ---------------- bf16 split mma.sync dual GEMM: [yl|yr] = X @ [Wl|Wr]^T ----------------
// Block tile: BM=128 rows x 64 cols. 4-stage cp.async k-pipeline (K=32 per stage).
// XOR bank-swizzle (chunk c stored at c ^ ((row>>1)&3)) -> PP=16, no padding.
// SMEM 96KB -> 2 CTAs/SM. 8 warps: 4(M) x 2(N), warp tile 32x32 via m16n8k16.
// acc += AhiBhi + AloBhi + AhiBlo  (drops lo*lo ~ 2^-18).
template <int DOUT>
__global__ void __launch_bounds__(256, 2)
tc_gemm_kernel(int wrow0)
{
    constexpr int XLOo = 2048;              // u32 offsets within a stage
    constexpr int WHIo = 4096;
    constexpr int WLOo = 5120;
    constexpr int SSZ  = 6144;              // u32 per stage
    // total 4 stages * 6144 u32 = 98304 bytes

    extern __shared__ uint32_t sm[];

    const int tid   = threadIdx.x;
    const int lane  = tid & 31;
    const int wid   = tid >> 5;
    const int mwarp = wid & 3;              // 0..3
    const int nwarp = wid >> 2;             // 0..1
    const int row0  = blockIdx.x * 128;
    const int col0  = blockIdx.y * 64;      // within [0, 2*DOUT)
    const uint32_t sbase = (uint32_t)__cvta_generic_to_shared(sm);

    // ---- issue all 4 k-stages via cp.async ----
#pragma unroll
    for (int kk = 0; kk < 4; kk++) {
        const uint32_t st = (uint32_t)kk * SSZ;
        // X: 128 rows x 4 chunks (16B) per component
        for (int idx = tid; idx < 512; idx += 256) {
            int r = idx >> 2, c = idx & 3;
            int grow = row0 + r;
            bool v = (grow < NN);
            int cs = c ^ ((r >> 1) & 3);
            cp16(sbase + (st + r * 16 + 4 * cs) * 4u,
                 g_xhi + grow * 64 + kk * 16 + c * 4, v);
            cp16(sbase + (st + XLOo + r * 16 + 4 * cs) * 4u,
                 g_xlo + grow * 64 + kk * 16 + c * 4, v);
        }
        // W: 64 rows x 4 chunks per component
        for (int idx = tid; idx < 256; idx += 256) {
            int r = idx >> 2, c = idx & 3;
            int cs = c ^ ((r >> 1) & 3);
            int wrow = wrow0 + col0 + r;
            cp16(sbase + (st + WHIo + r * 16 + 4 * cs) * 4u,
                 g_whi + wrow * 64 + kk * 16 + c * 4, true);
            cp16(sbase + (st + WLOo + r * 16 + 4 * cs) * 4u,
                 g_wlo + wrow * 64 + kk * 16 + c * 4, true);
        }
        cp_commit();
    }

    // per-lane invariants
    const int a_rowoff = (lane & 15);
    const int a_hi4    = lane >> 4;              // A chunk bit
    const int b_rowoff = ((lane >> 4) << 3) + (lane & 7);
    const int b_hi     = (lane & 8) ? 1 : 0;     // B chunk bit

    const int r8 = lane >> 2;    // 0..7
    const int c4 = lane & 3;     // 0..3

    float acc[2][4][4];
#pragma unroll
    for (int mt = 0; mt < 2; mt++)
#pragma unroll
        for (int nt = 0; nt < 4; nt++)
#pragma unroll
            for (int j = 0; j < 4; j++) acc[mt][nt][j] = 0.f;

    auto do_stage = [&](int s) {
        const uint32_t stB = sbase + (uint32_t)s * SSZ * 4u;
#pragma unroll
        for (int ktl = 0; ktl < 2; ktl++) {
            uint32_t ahi[2][4], alo[2][4];
#pragma unroll
            for (int mt = 0; mt < 2; mt++) {
                int row = mwarp * 32 + mt * 16 + a_rowoff;
                int cs  = (2 * ktl + a_hi4) ^ ((row >> 1) & 3);
                uint32_t ao = stB + (uint32_t)(row * 16 + 4 * cs) * 4u;
                ldsm_x4(ahi[mt][0], ahi[mt][1], ahi[mt][2], ahi[mt][3], ao);
                ldsm_x4(alo[mt][0], alo[mt][1], alo[mt][2], alo[mt][3], ao + XLOo * 4u);
            }
            uint32_t bhi[4][2], blo[4][2];
#pragma unroll
            for (int np = 0; np < 2; np++) {
                int row = nwarp * 32 + np * 16 + b_rowoff;
                int cs  = (2 * ktl + b_hi) ^ ((row >> 1) & 3);
                uint32_t bo = stB + (uint32_t)(WHIo + row * 16 + 4 * cs) * 4u;
                ldsm_x4(bhi[np*2][0], bhi[np*2][1], bhi[np*2+1][0], bhi[np*2+1][1], bo);
                ldsm_x4(blo[np*2][0], blo[np*2][1], blo[np*2+1][0], blo[np*2+1][1],
                        bo + (WLOo - WHIo) * 4u);
            }
#pragma unroll
            for (int mt = 0; mt < 2; mt++)
#pragma unroll
                for (int nt = 0; nt < 4; nt++) {
                    mma_bf16(acc[mt][nt], ahi[mt], bhi[nt]);
                    mma_bf16(acc[mt][nt], alo[mt], bhi[nt]);
                    mma_bf16(acc[mt][nt], ahi[mt], blo[nt]);
                }
        }
    };

    cp_wait<3>(); __syncthreads(); do_stage(0);
    cp_wait<2>(); __syncthreads(); do_stage(1);
    cp_wait<1>(); __syncthreads(); do_stage(2);
    cp_wait<0>(); __syncthreads(); do_stage(3);

    // ---- epilogue: scatter accumulators to g_yl / g_yr ----
#pragma unroll
    for (int mt = 0; mt < 2; mt++) {
        int rowg0 = row0 + mwarp * 32 + mt * 16 + r8;
#pragma unroll
        for (int nt = 0; nt < 4; nt++) {
            int colq = col0 + nwarp * 32 + nt * 8 + 2 * c4;   // within D2
            float* dstbase;
            int col;
            if (colq < DOUT) { dstbase = g_yl; col = colq; }
            else             { dstbase = g_yr; col = colq - DOUT; }
            if (rowg0 < NN)
                *(float2*)(dstbase + rowg0 * DOUT + col)
                    = make_float2(acc[mt][nt][0], acc[mt][nt][1]);
            if (rowg0 + 8 < NN)
                *(float2*)(dstbase + (rowg0 + 8) * DOUT + col)
                    = make_float2(acc[mt][nt][2], acc[mt][nt][3]);
        }
    }
}

// ---------------- fused CSR gather + mean + bias + root + BN + ReLU -> split h ----------------
__global__ void gather_fin128_kernel(const float* __restrict__ bl,
                                     const float* __restrict__ g,
                                     const float* __restrict__ b,
                                     const float* __restrict__ rm,
                                     const float* __restrict__ rv)
{
    int w    = (blockIdx.x * blockDim.x + threadIdx.x) >> 5;
    int lane = threadIdx.x & 31;
    if (w >= NN) return;

    int beg = g_rowptr[w];
    int end = g_rowptr[w + 1];

    const float4* yl4 = (const float4*)g_yl;
    float4 acc = make_float4(0.f, 0.f, 0.f, 0.f);

    for (int base = beg; base < end; base += 32) {
        int n  = min(32, end - base);
        int id = (base + lane < end) ? g_adj[base + lane] : 0;
#pragma unroll 8
        for (int j = 0; j < n; j++) {
            int s = __shfl_sync(0xffffffffu, id, j);
            float4 v = yl4[s * 32 + lane];
            acc.x += v.x; acc.y += v.y; acc.z += v.z; acc.w += v.w;
        }
    }

    float inv = (end > beg) ? 1.0f / (float)(end - beg) : 1.0f;

    float4 BL = ((const float4*)bl)[lane];
    float4 G  = ((const float4*)g )[lane];
    float4 B  = ((const float4*)b )[lane];
    float4 RM = ((const float4*)rm)[lane];
    float4 RV = ((const float4*)rv)[lane];
    float4 y  = ((const float4*)g_yr)[w * 32 + lane];

    float sx = G.x * rsqrtf(RV.x + 1e-5f);
    float sy = G.y * rsqrtf(RV.y + 1e-5f);
    float sz = G.z * rsqrtf(RV.z + 1e-5f);
    float sw = G.w * rsqrtf(RV.w + 1e-5f);

    float ox = fmaxf((acc.x * inv + BL.x + y.x - RM.x) * sx + B.x, 0.f);
    float oy = fmaxf((acc.y * inv + BL.y + y.y - RM.y) * sy + B.y, 0.f);
    float oz = fmaxf((acc.z * inv + BL.z + y.z - RM.z) * sz + B.z, 0.f);
    float ow = fmaxf((acc.w * inv + BL.w + y.w - RM.w) * sw + B.w, 0.f);

    // write next-layer features pre-split (hi/lo bf16x2)
    uint32_t h0, l0, h1, l1;
    split_bf16x2(ox, oy, h0, l0);
    split_bf16x2(oz, ow, h1, l1);
    g_xhi[w * 64 + 2 * lane]     = h0;
    g_xhi[w * 64 + 2 * lane + 1] = h1;
    g_xlo[w * 64 + 2 * lane]     = l0;
    g_xlo[w * 64 + 2 * lane + 1] = l1;
}

// ---------------- layer 2: fused gather + finalize + row L2 normalize -> out ----------------
__global__ void gather_fin64_norm_kernel(const float* __restrict__ bl,
                                         const float* __restrict__ g,
                                         const float* __restrict__ b,
                                         const float* __restrict__ rm,
                                         const float* __restrict__ rv,
                                         float* __restrict__ out)
{
    int w    = (blockIdx.x * blockDim.x + threadIdx.x) >> 5;
    int lane = threadIdx.x & 31;
    if (w >= NN) return;

    int beg = g_rowptr[w];
    int end = g_rowptr[w + 1];

    const float2* yl2 = (const float2*)g_yl;
    float2 acc = make_float2(0.f, 0.f);

    for (int base = beg; base < end; base += 32) {
        int n  = min(32, end - base);
        int id = (base + lane < end) ? g_adj[base + lane] : 0;
#pragma unroll 8
        for (int j = 0; j < n; j++) {
            int s = __shfl_sync(0xffffffffu, id, j);
            float2 v = yl2[s * 32 + lane];
            acc.x += v.x; acc.y += v.y;
        }
    }

    float inv = (end > beg) ? 1.0f / (float)(end - beg) : 1.0f;

    float2 BL = ((const float2*)bl)[lane];
    float2 G  = ((const float2*)g )[lane];
    float2 B  = ((const float2*)b )[lane];
    float2 RM = ((const float2*)rm)[lane];
    float2 RV = ((const float2*)rv)[lane];
    float2 y  = ((const float2*)g_yr)[w * 32 + lane];

    float v0 = (acc.x * inv + BL.x + y.x - RM.x) * (G.x * rsqrtf(RV.x + 1e-5f)) + B.x;
    float v1 = (acc.y * inv + BL.y + y.y - RM.y) * (G.y * rsqrtf(RV.y + 1e-5f)) + B.y;

    float s = v0 * v0 + v1 * v1;
#pragma unroll
    for (int off = 16; off > 0; off >>= 1)
        s += __shfl_xor_sync(0xffffffffu, s, off);

    float scale = 1.0f / fmaxf(sqrtf(s), 1e-12f);
    ((float2*)out)[w * 32 + lane] = make_float2(v0 * scale, v1 * scale);
}

// ---------------- launch ----------------
extern "C" void kernel_launch(void* const* d_in, const int* in_sizes, int n_in,
                              void* d_out, int out_size)
{
    const float* x  = (const float*)d_in[0];
    const int*   ei = (const int*)d_in[1];
    auto P = [&](int layer, int j) { return (const float*)d_in[2 + layer * 7 + j]; };
    // j: 0=Wl, 1=bl, 2=Wr, 3=g, 4=b, 5=rm, 6=rv

    // one-time stream/event setup (created before graph capture on first call)
    static cudaStream_t s2 = [] {
        cudaStream_t s; cudaStreamCreateWithFlags(&s, cudaStreamNonBlocking); return s;
    }();
    static cudaEvent_t e1 = [] {
        cudaEvent_t e; cudaEventCreateWithFlags(&e, cudaEventDisableTiming); return e;
    }();
    static cudaEvent_t e2 = [] {
        cudaEvent_t e; cudaEventCreateWithFlags(&e, cudaEventDisableTiming); return e;
    }();

    const int SMEM = 4 * 6144 * 4;  // 98304 bytes -> 2 CTAs/SM
    cudaFuncSetAttribute(tc_gemm_kernel<128>, cudaFuncAttributeMaxDynamicSharedMemorySize, SMEM);
    cudaFuncSetAttribute(tc_gemm_kernel<64>,  cudaFuncAttributeMaxDynamicSharedMemorySize, SMEM);

    const int NT = (NN + 127) / 128;   // 391 M-tiles
    const int COMBO_N = NN * 32 + 640 * 32 + EE;

    // (1) split x+weights AND degree histogram (fused) — main stream
    split_hist_kernel<<<(COMBO_N + 255) / 256, 256>>>(x, P(0,0), P(0,2), P(1,0), P(1,2),
                                                      P(2,0), P(2,2), ei);
    cudaEventRecord(e1, 0);

    // (2-3) CSR: scan + fill — main stream
    scan_kernel<<<1, 1024>>>();
    fill_kernel<<<(EE + 255) / 256, 256>>>(ei);

    // (4) layer-0 GEMM on side stream, concurrent with scan+fill
    cudaStreamWaitEvent(s2, e1, 0);
    tc_gemm_kernel<128><<<dim3(NT, 4), 256, SMEM, s2>>>(0);
    cudaEventRecord(e2, s2);

    // join: gather0 needs fill (main) + gemm0 (s2)
    cudaStreamWaitEvent(0, e2, 0);
    gather_fin128_kernel<<<(NN + 7) / 8, 256>>>(P(0,1), P(0,3), P(0,4), P(0,5), P(0,6));

    // layer 1 (serial)
    tc_gemm_kernel<128><<<dim3(NT, 4), 256, SMEM>>>(256);
    gather_fin128_kernel<<<(NN + 7) / 8, 256>>>(P(1,1), P(1,3), P(1,4), P(1,5), P(1,6));

    // layer 2 (serial)
    tc_gemm_kernel<64><<<dim3(NT, 2), 256, SMEM>>>(512);
    gather_fin64_norm_kernel<<<(NN + 7) / 8, 256>>>(P(2,1), P(2,3), P(2,4), P(2,5), P(2,6),
                                                    (float*)d_out);
}